// round 15
// baseline (speedup 1.0000x reference)
#include <cuda_runtime.h>
#include <cuda_fp16.h>
#include <cstdint>

#define MDIM 16384
#define NDIM 1024
#define KDIM 4096

#define BM 128
#define BN 128
#define BK 64
#define KT (KDIM / BK)              // 64 k-tiles
#define ROWB 144                    // 64 halves + 8 pad = 144 B
#define TILE (BM * ROWB)            // 18432 per tile (A16 or B)
#define HDR 1024
#define SMEM_BYTES (HDR + 5 * TILE) // 93184 (x2 CTAs = 182 KB <= 228 KB)

// ---------------- device scratch ----------------
__device__ __align__(16) uint16_t g_w[(size_t)NDIM * KDIM];   // fp16 w_int (8 MB)
__device__ float g_scale[NDIM];

// ---------------- PTX helpers ----------------
__device__ __forceinline__ uint32_t smem_u32(const void* p) {
    uint32_t a;
    asm("{ .reg .u64 t; cvta.to.shared.u64 t, %1; cvt.u32.u64 %0, t; }" : "=r"(a) : "l"(p));
    return a;
}
__device__ __forceinline__ void cp16(uint32_t dst, const void* src) {
    asm volatile("cp.async.cg.shared.global [%0], [%1], 16;" :: "r"(dst), "l"(src));
}
__device__ __forceinline__ void cp_commit() {
    asm volatile("cp.async.commit_group;" ::: "memory");
}
template <int N> __device__ __forceinline__ void cp_wait() {
    asm volatile("cp.async.wait_group %0;" :: "n"(N) : "memory");
}
__device__ __forceinline__ void ldsm4(uint32_t& r0, uint32_t& r1, uint32_t& r2, uint32_t& r3,
                                      uint32_t addr) {
    asm volatile("ldmatrix.sync.aligned.m8n8.x4.shared.b16 {%0,%1,%2,%3}, [%4];"
                 : "=r"(r0), "=r"(r1), "=r"(r2), "=r"(r3) : "r"(addr));
}
__device__ __forceinline__ void mma16816(float& d0, float& d1, float& d2, float& d3,
                                         uint32_t a0, uint32_t a1, uint32_t a2, uint32_t a3,
                                         uint32_t b0, uint32_t b1) {
    asm volatile(
        "mma.sync.aligned.m16n8k16.row.col.f32.f16.f16.f32 "
        "{%0,%1,%2,%3}, {%4,%5,%6,%7}, {%8,%9}, {%0,%1,%2,%3};"
        : "+f"(d0), "+f"(d1), "+f"(d2), "+f"(d3)
        : "r"(a0), "r"(a1), "r"(a2), "r"(a3), "r"(b0), "r"(b1));
}

// ---------------- kernel 1: W fake-quant only (~24 MB traffic, ~6 us) ----------------
__global__ void prep_kernel(const float* __restrict__ W) {
    int tid = threadIdx.x;
    int d = blockIdx.x;
    const float4* row4 = reinterpret_cast<const float4*>(W + (size_t)d * KDIM);
    float4 f[4];
    float m = 0.f;
    #pragma unroll
    for (int i = 0; i < 4; i++) {
        f[i] = row4[i * 256 + tid];
        m = fmaxf(m, fmaxf(fmaxf(fabsf(f[i].x), fabsf(f[i].y)),
                           fmaxf(fabsf(f[i].z), fabsf(f[i].w))));
    }
    #pragma unroll
    for (int o = 16; o; o >>= 1) m = fmaxf(m, __shfl_xor_sync(0xffffffffu, m, o));
    __shared__ float red[8];
    if ((tid & 31) == 0) red[tid >> 5] = m;
    __syncthreads();
    if (tid < 8) {
        float v = red[tid];
        #pragma unroll
        for (int o = 4; o; o >>= 1) v = fmaxf(v, __shfl_xor_sync(0xffu, v, o));
        if (tid == 0) red[0] = v;
    }
    __syncthreads();
    float scale = fmaxf(red[0], 1e-8f) / 127.f;
    if (tid == 0) g_scale[d] = scale;
    uint2* wout = reinterpret_cast<uint2*>(g_w + (size_t)d * KDIM);
    #pragma unroll
    for (int i = 0; i < 4; i++) {
        float qx = fminf(fmaxf(rintf(f[i].x / scale), -128.f), 127.f);
        float qy = fminf(fmaxf(rintf(f[i].y / scale), -128.f), 127.f);
        float qz = fminf(fmaxf(rintf(f[i].z / scale), -128.f), 127.f);
        float qw = fminf(fmaxf(rintf(f[i].w / scale), -128.f), 127.f);
        __half2 lo = __floats2half2_rn(qx, qy);        // exact ints in fp16
        __half2 hi = __floats2half2_rn(qz, qw);
        uint2 o;
        o.x = *reinterpret_cast<uint32_t*>(&lo);
        o.y = *reinterpret_cast<uint32_t*>(&hi);
        wout[i * 256 + tid] = o;
    }
}

// ---------------- kernel 2: GEMM reading A as fp32, converting in-loop ----------------
// smem: [0,512) scale, [512,1024) bias, B stages @ HDR + {0,1,2}*TILE,
//       A16 double buffer @ HDR + {3,4}*TILE.
__device__ __forceinline__ void ldgsts_b(uint32_t sb, int s, int tid, int n0, int t) {
    uint32_t base = sb + HDR + (uint32_t)s * TILE;
    int k0 = t * BK;
    #pragma unroll
    for (int i = 0; i < 4; i++) {                 // 1024 16B-chunks over 256 threads
        int cid = i * 256 + tid;
        int row = cid >> 3, col = cid & 7;
        cp16(base + (uint32_t)(row * ROWB + col * 16),
             reinterpret_cast<const __half*>(g_w) + (size_t)(n0 + row) * KDIM + k0 + col * 8);
    }
}
// Load one 16-float chunk of next A tile (per-thread).
__device__ __forceinline__ void ldg_a(float4 f[4], const float* __restrict__ H,
                                      int m0, int arow, int ahalf, int t, int chunk) {
    const float4* p = reinterpret_cast<const float4*>(
        H + (size_t)(m0 + arow) * KDIM + t * BK + ahalf * 32 + chunk * 16);
    f[0] = p[0]; f[1] = p[1]; f[2] = p[2]; f[3] = p[3];
}
// Convert 16 floats -> 16 halves and store 2x16B into A16 buffer.
__device__ __forceinline__ void cvt_sts(char* smem, uint32_t a16_off, const float4 f[4],
                                        int arow, int ahalf, int chunk) {
    uint4* dst = reinterpret_cast<uint4*>(
        smem + a16_off + arow * ROWB + (ahalf * 4 + chunk * 2) * 16);
    #pragma unroll
    for (int j = 0; j < 2; j++) {
        __half2 h0 = __floats2half2_rn(f[2 * j].x, f[2 * j].y);
        __half2 h1 = __floats2half2_rn(f[2 * j].z, f[2 * j].w);
        __half2 h2 = __floats2half2_rn(f[2 * j + 1].x, f[2 * j + 1].y);
        __half2 h3 = __floats2half2_rn(f[2 * j + 1].z, f[2 * j + 1].w);
        uint4 v;
        v.x = *reinterpret_cast<uint32_t*>(&h0);
        v.y = *reinterpret_cast<uint32_t*>(&h1);
        v.z = *reinterpret_cast<uint32_t*>(&h2);
        v.w = *reinterpret_cast<uint32_t*>(&h3);
        dst[j] = v;
    }
}

__global__ void __launch_bounds__(256, 2) gemm_kernel(const float* __restrict__ H,
                                                      const float* __restrict__ bias,
                                                      const float* __restrict__ input,
                                                      float* __restrict__ out) {
    extern __shared__ char smem[];
    uint32_t sb = smem_u32(smem);
    int tid = threadIdx.x;
    int wid = tid >> 5, lane = tid & 31;
    int g = lane >> 2, c = lane & 3;
    int wm = wid & 1, wn = wid >> 1;      // 2 x 4 warp grid, warp tile 64x32
    int arow = tid >> 1, ahalf = tid & 1; // A fp32 load coords (128 B per thread)

    int mtile = blockIdx.x >> 3;          // 128 m-tiles; 8 consecutive bids share A in L2
    int ntile = blockIdx.x & 7;
    int m0 = mtile * BM, n0 = ntile * BN;

    float* s_scale = reinterpret_cast<float*>(smem);
    float* s_bias  = reinterpret_cast<float*>(smem + 512);
    if (tid < 128) {
        s_scale[tid] = g_scale[n0 + tid];
        s_bias[tid]  = bias[n0 + tid];
    }

    uint32_t a_loff = (uint32_t)((wm * 64 + (lane & 15)) * ROWB + (lane >> 4) * 16);
    uint32_t b_loff = (uint32_t)((wn * 32 + (lane >> 4) * 8 + (lane & 7)) * ROWB +
                      (((lane >> 3) & 1) * 16));

    // prologue: B(0), B(1) via cp.async; A(0) via LDG->cvt->STS into A16[0]
    ldgsts_b(sb, 0, tid, n0, 0); cp_commit();
    ldgsts_b(sb, 1, tid, n0, 1); cp_commit();
    {
        float4 f0[4], f1[4];
        ldg_a(f0, H, m0, arow, ahalf, 0, 0);
        ldg_a(f1, H, m0, arow, ahalf, 0, 1);
        cvt_sts(smem, HDR + 3 * TILE, f0, arow, ahalf, 0);
        cvt_sts(smem, HDR + 3 * TILE, f1, arow, ahalf, 1);
    }

    float acc[4][4][4];
    #pragma unroll
    for (int mt = 0; mt < 4; mt++)
        #pragma unroll
        for (int nt = 0; nt < 4; nt++)
            #pragma unroll
            for (int r = 0; r < 4; r++) acc[mt][nt][r] = 0.f;

    for (int t = 0; t < KT; t++) {
        cp_wait<1>();                     // B(t) resident
        __syncthreads();                  // + A16[t&1] stores visible CTA-wide

        if (t + 2 < KT) ldgsts_b(sb, (t + 2) % 3, tid, n0, t + 2);
        cp_commit();

        bool pf = (t + 1 < KT);
        uint32_t nextA = HDR + (3 + ((t + 1) & 1)) * TILE;
        float4 af[4];
        if (pf) ldg_a(af, H, m0, arow, ahalf, t + 1, 0);    // chunk0 of next A

        uint32_t stageA = sb + HDR + (uint32_t)((3 + (t & 1)) * TILE);
        uint32_t stageB = sb + HDR + (uint32_t)((t % 3) * TILE);

        // ks = 0,1
        #pragma unroll
        for (int ks = 0; ks < 2; ks++) {
            uint32_t a[4][4], b[2][4];
            #pragma unroll
            for (int mt = 0; mt < 4; mt++)
                ldsm4(a[mt][0], a[mt][1], a[mt][2], a[mt][3],
                      stageA + a_loff + (uint32_t)(mt * 16 * ROWB) + (uint32_t)(ks * 32));
            #pragma unroll
            for (int p = 0; p < 2; p++)
                ldsm4(b[p][0], b[p][1], b[p][2], b[p][3],
                      stageB + b_loff + (uint32_t)(p * 16 * ROWB) + (uint32_t)(ks * 32));
            #pragma unroll
            for (int mt = 0; mt < 4; mt++)
                #pragma unroll
                for (int nt = 0; nt < 4; nt++) {
                    int p = nt >> 1, q = nt & 1;
                    mma16816(acc[mt][nt][0], acc[mt][nt][1], acc[mt][nt][2], acc[mt][nt][3],
                             a[mt][0], a[mt][1], a[mt][2], a[mt][3],
                             b[p][2 * q], b[p][2 * q + 1]);
                }
        }

        if (pf) {
            cvt_sts(smem, nextA, af, arow, ahalf, 0);       // LDG chunk0 landed (~2 ks ago)
            ldg_a(af, H, m0, arow, ahalf, t + 1, 1);        // chunk1 of next A
        }

        // ks = 2,3
        #pragma unroll
        for (int ks = 2; ks < 4; ks++) {
            uint32_t a[4][4], b[2][4];
            #pragma unroll
            for (int mt = 0; mt < 4; mt++)
                ldsm4(a[mt][0], a[mt][1], a[mt][2], a[mt][3],
                      stageA + a_loff + (uint32_t)(mt * 16 * ROWB) + (uint32_t)(ks * 32));
            #pragma unroll
            for (int p = 0; p < 2; p++)
                ldsm4(b[p][0], b[p][1], b[p][2], b[p][3],
                      stageB + b_loff + (uint32_t)(p * 16 * ROWB) + (uint32_t)(ks * 32));
            #pragma unroll
            for (int mt = 0; mt < 4; mt++)
                #pragma unroll
                for (int nt = 0; nt < 4; nt++) {
                    int p = nt >> 1, q = nt & 1;
                    mma16816(acc[mt][nt][0], acc[mt][nt][1], acc[mt][nt][2], acc[mt][nt][3],
                             a[mt][0], a[mt][1], a[mt][2], a[mt][3],
                             b[p][2 * q], b[p][2 * q + 1]);
                }
        }

        if (pf) cvt_sts(smem, nextA, af, arow, ahalf, 1);   // chunk1
    }

    // epilogue: out = acc * scale[n] + bias[n] + input
    #pragma unroll
    for (int mt = 0; mt < 4; mt++) {
        #pragma unroll
        for (int nt = 0; nt < 4; nt++) {
            int nl = wn * 32 + nt * 8 + 2 * c;
            int n  = n0 + nl;
            float sc0 = s_scale[nl], sc1 = s_scale[nl + 1];
            float bi0 = s_bias[nl],  bi1 = s_bias[nl + 1];
            int mA = m0 + wm * 64 + mt * 16 + g;
            int mB = mA + 8;

            const float2* inA = reinterpret_cast<const float2*>(input + (size_t)mA * NDIM + n);
            const float2* inB = reinterpret_cast<const float2*>(input + (size_t)mB * NDIM + n);
            float2* outA = reinterpret_cast<float2*>(out + (size_t)mA * NDIM + n);
            float2* outB = reinterpret_cast<float2*>(out + (size_t)mB * NDIM + n);

            float2 ia = *inA, ib = *inB, oa, ob;
            oa.x = acc[mt][nt][0] * sc0 + bi0 + ia.x;
            oa.y = acc[mt][nt][1] * sc1 + bi1 + ia.y;
            ob.x = acc[mt][nt][2] * sc0 + bi0 + ib.x;
            ob.y = acc[mt][nt][3] * sc1 + bi1 + ib.y;
            *outA = oa;
            *outB = ob;
        }
    }
}

// ---------------- launch ----------------
extern "C" void kernel_launch(void* const* d_in, const int* in_sizes, int n_in,
                              void* d_out, int out_size) {
    const float* hidden = (const float*)d_in[0];   // [16,1024,4096]
    const float* input  = (const float*)d_in[1];   // [16,1024,1024]
    const float* W      = (const float*)d_in[2];   // [1024,4096]
    const float* b      = (const float*)d_in[3];   // [1024]
    float* out = (float*)d_out;

    prep_kernel<<<NDIM, 256>>>(W);

    cudaFuncSetAttribute(gemm_kernel, cudaFuncAttributeMaxDynamicSharedMemorySize, SMEM_BYTES);
    gemm_kernel<<<(MDIM / BM) * (NDIM / BN), 256, SMEM_BYTES>>>(hidden, b, input, out);
}

// round 16
// speedup vs baseline: 1.6495x; 1.6495x over previous
#include <cuda_runtime.h>
#include <cuda_fp16.h>
#include <cstdint>

#define MDIM 16384
#define NDIM 1024
#define KDIM 4096

#define BM 128
#define BN 128
#define BK 64
#define NSTAGE 3
#define KT (KDIM / BK)              // 64 k-tiles
#define NTILES ((MDIM / BM) * (NDIM / BN))   // 1024 tiles
#define GRID 296
#define NCONS 148                   // consumer CTAs (one per SM)
#define NPROD 148                   // producer CTAs
#define NMB (MDIM / BM)             // 128 H m-blocks
#define NSLICE (NMB * 8)            // 1024 slices of 16 rows
#define SSTRIDE 72
#define ROWB (SSTRIDE * 2)          // 144 B
#define A_STAGE_B (BM * ROWB)       // 18432
#define STAGE_B   (2 * A_STAGE_B)   // 36864
#define HDR 1056
#define SMEM_BYTES (HDR + NSTAGE * STAGE_B)   // 111648 (x2 CTAs fits 228KB)

// ---------------- device scratch ----------------
__device__ __align__(16) uint16_t g_h[(size_t)MDIM * KDIM];   // fp16 hidden (128 MB)
__device__ __align__(16) uint16_t g_w[(size_t)NDIM * KDIM];   // fp16 w_int  (8 MB)
__device__ float g_scale[NDIM];
__device__ unsigned g_cnt[NMB];     // per-block slice counters (ready when == 8)
__device__ unsigned g_wctr;         // consumer CTAs done with W quant
__device__ unsigned g_tile_ctr;

// ---------------- PTX helpers ----------------
__device__ __forceinline__ uint32_t smem_u32(const void* p) {
    uint32_t a;
    asm("{ .reg .u64 t; cvta.to.shared.u64 t, %1; cvt.u32.u64 %0, t; }" : "=r"(a) : "l"(p));
    return a;
}
__device__ __forceinline__ void cp16(uint32_t dst, const void* src) {
    asm volatile("cp.async.cg.shared.global [%0], [%1], 16;" :: "r"(dst), "l"(src));
}
__device__ __forceinline__ void cp_commit() {
    asm volatile("cp.async.commit_group;" ::: "memory");
}
template <int N> __device__ __forceinline__ void cp_wait() {
    asm volatile("cp.async.wait_group %0;" :: "n"(N) : "memory");
}
__device__ __forceinline__ void ldsm4(uint32_t& r0, uint32_t& r1, uint32_t& r2, uint32_t& r3,
                                      uint32_t addr) {
    asm volatile("ldmatrix.sync.aligned.m8n8.x4.shared.b16 {%0,%1,%2,%3}, [%4];"
                 : "=r"(r0), "=r"(r1), "=r"(r2), "=r"(r3) : "r"(addr));
}
__device__ __forceinline__ void mma16816(float& d0, float& d1, float& d2, float& d3,
                                         uint32_t a0, uint32_t a1, uint32_t a2, uint32_t a3,
                                         uint32_t b0, uint32_t b1) {
    asm volatile(
        "mma.sync.aligned.m16n8k16.row.col.f32.f16.f16.f32 "
        "{%0,%1,%2,%3}, {%4,%5,%6,%7}, {%8,%9}, {%0,%1,%2,%3};"
        : "+f"(d0), "+f"(d1), "+f"(d2), "+f"(d3)
        : "r"(a0), "r"(a1), "r"(a2), "r"(a3), "r"(b0), "r"(b1));
}

// ---------------- init kernel (runs each launch/replay) ----------------
__global__ void init_kernel() {
    int tid = threadIdx.x;
    if (tid < NMB) g_cnt[tid] = 0u;
    if (tid == 0) { g_wctr = 0u; g_tile_ctr = 0u; }
}

// ---------------- producers ----------------
// Convert one 16-row slice of H m-block mb (STG.128).
__device__ void convert_slice(const float* __restrict__ H, int mb, int p) {
    int tid = threadIdx.x;
    size_t fbase = ((size_t)mb * BM + p * 16) * KDIM / 4;   // float4 index of slice start
    const float4* src = reinterpret_cast<const float4*>(H) + fbase;
    uint4* dst = reinterpret_cast<uint4*>(reinterpret_cast<uint2*>(g_h) + fbase);
    #pragma unroll 8
    for (int i = tid; i < 16 * KDIM / 8; i += 256) {
        float4 v0 = src[2 * i];
        float4 v1 = src[2 * i + 1];
        __half2 h0 = __floats2half2_rn(v0.x, v0.y);
        __half2 h1 = __floats2half2_rn(v0.z, v0.w);
        __half2 h2 = __floats2half2_rn(v1.x, v1.y);
        __half2 h3 = __floats2half2_rn(v1.z, v1.w);
        uint4 o;
        o.x = *reinterpret_cast<uint32_t*>(&h0);
        o.y = *reinterpret_cast<uint32_t*>(&h1);
        o.z = *reinterpret_cast<uint32_t*>(&h2);
        o.w = *reinterpret_cast<uint32_t*>(&h3);
        dst[i] = o;
    }
}

// Quantize one W output-channel row (whole CTA).
__device__ void quant_w_row(const float* __restrict__ W, int d) {
    int tid = threadIdx.x;
    const float4* row4 = reinterpret_cast<const float4*>(W + (size_t)d * KDIM);
    float4 f[4];
    float m = 0.f;
    #pragma unroll
    for (int i = 0; i < 4; i++) {
        f[i] = row4[i * 256 + tid];
        m = fmaxf(m, fmaxf(fmaxf(fabsf(f[i].x), fabsf(f[i].y)),
                           fmaxf(fabsf(f[i].z), fabsf(f[i].w))));
    }
    #pragma unroll
    for (int o = 16; o; o >>= 1) m = fmaxf(m, __shfl_xor_sync(0xffffffffu, m, o));
    __shared__ float red[8];
    if ((tid & 31) == 0) red[tid >> 5] = m;
    __syncthreads();
    if (tid < 8) {
        float v = red[tid];
        #pragma unroll
        for (int o = 4; o; o >>= 1) v = fmaxf(v, __shfl_xor_sync(0xffu, v, o));
        if (tid == 0) red[0] = v;
    }
    __syncthreads();
    float scale = fmaxf(red[0], 1e-8f) / 127.f;
    if (tid == 0) g_scale[d] = scale;
    uint2* wout = reinterpret_cast<uint2*>(g_w + (size_t)d * KDIM);
    #pragma unroll
    for (int i = 0; i < 4; i++) {
        float qx = fminf(fmaxf(rintf(f[i].x / scale), -128.f), 127.f);
        float qy = fminf(fmaxf(rintf(f[i].y / scale), -128.f), 127.f);
        float qz = fminf(fmaxf(rintf(f[i].z / scale), -128.f), 127.f);
        float qw = fminf(fmaxf(rintf(f[i].w / scale), -128.f), 127.f);
        __half2 lo = __floats2half2_rn(qx, qy);        // exact ints in fp16
        __half2 hi = __floats2half2_rn(qz, qw);
        uint2 o;
        o.x = *reinterpret_cast<uint32_t*>(&lo);
        o.y = *reinterpret_cast<uint32_t*>(&hi);
        wout[i * 256 + tid] = o;
    }
    __syncthreads();   // red[] reuse safety across rows
}

// ---------------- GEMM stage load (R4 schedule) ----------------
__device__ __forceinline__ void load_stage(uint32_t stage_base, int tid, int m0, int n0, int t) {
    int k0 = t * BK;
    const __half* Ab = reinterpret_cast<const __half*>(g_h) + (size_t)m0 * KDIM + k0;
    #pragma unroll
    for (int i = 0; i < 4; i++) {
        int cid = i * 256 + tid;
        int row = cid >> 3, col = cid & 7;
        cp16(stage_base + row * ROWB + col * 16, Ab + (size_t)row * KDIM + col * 8);
    }
    const __half* Bb = reinterpret_cast<const __half*>(g_w) + (size_t)n0 * KDIM + k0;
    uint32_t bbase = stage_base + A_STAGE_B;
    #pragma unroll
    for (int i = 0; i < 4; i++) {
        int cid = i * 256 + tid;
        int row = cid >> 3, col = cid & 7;
        cp16(bbase + row * ROWB + col * 16, Bb + (size_t)row * KDIM + col * 8);
    }
}

__global__ void __launch_bounds__(256, 2) fused_kernel(const float* __restrict__ H,
                                                       const float* __restrict__ W,
                                                       const float* __restrict__ bias,
                                                       const float* __restrict__ input,
                                                       float* __restrict__ out) {
    extern __shared__ char smem[];
    uint32_t sb = smem_u32(smem);
    int tid = threadIdx.x;
    int bid = blockIdx.x;
    int wid = tid >> 5, lane = tid & 31;
    int g = lane >> 2, c = lane & 3;
    int wm = wid & 1, wn = wid >> 1;      // 2 x 4 warp grid, warp tile 64x32

    float* s_scale = reinterpret_cast<float*>(smem);
    float* s_bias  = reinterpret_cast<float*>(smem + 512);
    unsigned* s_tile = reinterpret_cast<unsigned*>(smem + 1024);

    uint32_t a_loff = (uint32_t)((wm * 64 + (lane & 15)) * ROWB + (lane >> 4) * 16);
    uint32_t b_loff = (uint32_t)(A_STAGE_B +
                      (wn * 32 + (lane >> 4) * 8 + (lane & 7)) * ROWB +
                      (((lane >> 3) & 1) * 16));

    if (bid >= NCONS) {
        // ---- PRODUCER: convert all H slices in block order, then join GEMM ----
        for (int s = bid - NCONS; s < NSLICE; s += NPROD) {
            convert_slice(H, s >> 3, s & 7);
            __threadfence();
            __syncthreads();
            if (tid == 0) atomicAdd(&g_cnt[s >> 3], 1u);
            __syncthreads();
        }
        // W is long done by now (consumers quantize it in ~6us); verify cheaply.
        if (tid == 0) {
            while (*((volatile unsigned*)&g_wctr) < NCONS) { }
            __threadfence();
        }
        __syncthreads();
    } else {
        // ---- CONSUMER: cooperative W quant, then barrier ----
        for (int r = bid; r < NDIM; r += NCONS) quant_w_row(W, r);
        __threadfence();
        __syncthreads();
        if (tid == 0) {
            atomicAdd(&g_wctr, 1u);
            while (*((volatile unsigned*)&g_wctr) < NCONS) { }
            __threadfence();
        }
        __syncthreads();
    }

    // ---- persistent tile sweep (everyone) ----
    while (true) {
        __syncthreads();                  // prior tile done (s_scale/s_tile reuse)
        if (tid == 0) *s_tile = atomicAdd(&g_tile_ctr, 1u);
        __syncthreads();
        unsigned tile = *s_tile;
        if (tile >= NTILES) break;

        int mt = (int)(tile >> 3);
        int nt_ = (int)(tile & 7);
        int m0 = mt * BM, n0 = nt_ * BN;

        // wait for this tile's A block (supply outruns demand after startup)
        if (tid == 0) {
            while (*((volatile unsigned*)&g_cnt[mt]) < 8u) { }
            __threadfence();
        }
        if (tid < 128) {
            s_scale[tid] = g_scale[n0 + tid];
            s_bias[tid]  = bias[n0 + tid];
        }
        __syncthreads();

        // prologue: fill 3 stages
        #pragma unroll
        for (int s = 0; s < NSTAGE; s++) {
            load_stage(sb + HDR + (uint32_t)s * STAGE_B, tid, m0, n0, s);
            cp_commit();
        }

        float acc[4][4][4];
        #pragma unroll
        for (int mt2 = 0; mt2 < 4; mt2++)
            #pragma unroll
            for (int nt2 = 0; nt2 < 4; nt2++)
                #pragma unroll
                for (int r = 0; r < 4; r++) acc[mt2][nt2][r] = 0.f;

        for (int t = 0; t < KT; t++) {
            uint32_t stage = sb + HDR + (uint32_t)(t % NSTAGE) * STAGE_B;

            cp_wait<NSTAGE - 1>();
            __syncthreads();

            #pragma unroll
            for (int ks = 0; ks < 4; ks++) {
                uint32_t a[4][4], b[2][4];
                #pragma unroll
                for (int mt2 = 0; mt2 < 4; mt2++)
                    ldsm4(a[mt2][0], a[mt2][1], a[mt2][2], a[mt2][3],
                          stage + a_loff + (uint32_t)(mt2 * 16 * ROWB) + (uint32_t)(ks * 32));
                #pragma unroll
                for (int p = 0; p < 2; p++)
                    ldsm4(b[p][0], b[p][1], b[p][2], b[p][3],
                          stage + b_loff + (uint32_t)(p * 16 * ROWB) + (uint32_t)(ks * 32));
                #pragma unroll
                for (int mt2 = 0; mt2 < 4; mt2++)
                    #pragma unroll
                    for (int nt2 = 0; nt2 < 4; nt2++) {
                        int p = nt2 >> 1, q = nt2 & 1;
                        mma16816(acc[mt2][nt2][0], acc[mt2][nt2][1],
                                 acc[mt2][nt2][2], acc[mt2][nt2][3],
                                 a[mt2][0], a[mt2][1], a[mt2][2], a[mt2][3],
                                 b[p][2 * q], b[p][2 * q + 1]);
                    }
            }

            __syncthreads();
            if (t + NSTAGE < KT)
                load_stage(stage, tid, m0, n0, t + NSTAGE);
            cp_commit();
        }

        // epilogue: out = acc * scale[n] + bias[n] + input
        #pragma unroll
        for (int mt2 = 0; mt2 < 4; mt2++) {
            #pragma unroll
            for (int nt2 = 0; nt2 < 4; nt2++) {
                int nl = wn * 32 + nt2 * 8 + 2 * c;
                int n  = n0 + nl;
                float sc0 = s_scale[nl], sc1 = s_scale[nl + 1];
                float bi0 = s_bias[nl],  bi1 = s_bias[nl + 1];
                int mA = m0 + wm * 64 + mt2 * 16 + g;
                int mB = mA + 8;

                const float2* inA = reinterpret_cast<const float2*>(input + (size_t)mA * NDIM + n);
                const float2* inB = reinterpret_cast<const float2*>(input + (size_t)mB * NDIM + n);
                float2* outA = reinterpret_cast<float2*>(out + (size_t)mA * NDIM + n);
                float2* outB = reinterpret_cast<float2*>(out + (size_t)mB * NDIM + n);

                float2 ia = *inA, ib = *inB, oa, ob;
                oa.x = acc[mt2][nt2][0] * sc0 + bi0 + ia.x;
                oa.y = acc[mt2][nt2][1] * sc1 + bi1 + ia.y;
                ob.x = acc[mt2][nt2][2] * sc0 + bi0 + ib.x;
                ob.y = acc[mt2][nt2][3] * sc1 + bi1 + ib.y;
                *outA = oa;
                *outB = ob;
            }
        }
    }
}

// ---------------- launch ----------------
extern "C" void kernel_launch(void* const* d_in, const int* in_sizes, int n_in,
                              void* d_out, int out_size) {
    const float* hidden = (const float*)d_in[0];   // [16,1024,4096]
    const float* input  = (const float*)d_in[1];   // [16,1024,1024]
    const float* W      = (const float*)d_in[2];   // [1024,4096]
    const float* b      = (const float*)d_in[3];   // [1024]
    float* out = (float*)d_out;

    init_kernel<<<1, 256>>>();

    cudaFuncSetAttribute(fused_kernel, cudaFuncAttributeMaxDynamicSharedMemorySize, SMEM_BYTES);
    fused_kernel<<<GRID, 256, SMEM_BYTES>>>(hidden, W, b, input, out);
}

// round 17
// speedup vs baseline: 1.8200x; 1.1033x over previous
#include <cuda_runtime.h>
#include <cuda_fp16.h>
#include <cstdint>

#define MDIM 16384
#define NDIM 1024
#define KDIM 4096

#define BM 128
#define BN 128
#define BK 64
#define NSTAGE 3
#define KT (KDIM / BK)              // 64 k-tiles
#define SSTRIDE 72                  // halves per smem row (64 + 8 pad) -> 144 B
#define ROWB (SSTRIDE * 2)          // 144 bytes per row
#define A_STAGE_B (BM * ROWB)       // 18432
#define STAGE_B   (2 * A_STAGE_B)   // 36864 (A then B)
#define SMEM_BYTES (1024 + NSTAGE * STAGE_B)  // 111616 (x2 CTAs fits 228KB)

// ---------------- device scratch ----------------
__device__ __align__(16) uint16_t g_h[(size_t)MDIM * KDIM];   // fp16 hidden (128 MB)
__device__ __align__(16) uint16_t g_w[(size_t)NDIM * KDIM];   // fp16 w_int  (8 MB)
__device__ float g_scale[NDIM];

// ---------------- PTX helpers ----------------
__device__ __forceinline__ uint32_t smem_u32(const void* p) {
    uint32_t a;
    asm("{ .reg .u64 t; cvta.to.shared.u64 t, %1; cvt.u32.u64 %0, t; }" : "=r"(a) : "l"(p));
    return a;
}
__device__ __forceinline__ void cp16(uint32_t dst, const void* src) {
    asm volatile("cp.async.cg.shared.global [%0], [%1], 16;" :: "r"(dst), "l"(src));
}
__device__ __forceinline__ void cp_commit() {
    asm volatile("cp.async.commit_group;" ::: "memory");
}
template <int N> __device__ __forceinline__ void cp_wait() {
    asm volatile("cp.async.wait_group %0;" :: "n"(N) : "memory");
}
__device__ __forceinline__ void ldsm4(uint32_t& r0, uint32_t& r1, uint32_t& r2, uint32_t& r3,
                                      uint32_t addr) {
    asm volatile("ldmatrix.sync.aligned.m8n8.x4.shared.b16 {%0,%1,%2,%3}, [%4];"
                 : "=r"(r0), "=r"(r1), "=r"(r2), "=r"(r3) : "r"(addr));
}
__device__ __forceinline__ void mma16816(float& d0, float& d1, float& d2, float& d3,
                                         uint32_t a0, uint32_t a1, uint32_t a2, uint32_t a3,
                                         uint32_t b0, uint32_t b1) {
    asm volatile(
        "mma.sync.aligned.m16n8k16.row.col.f32.f16.f16.f32 "
        "{%0,%1,%2,%3}, {%4,%5,%6,%7}, {%8,%9}, {%0,%1,%2,%3};"
        : "+f"(d0), "+f"(d1), "+f"(d2), "+f"(d3)
        : "r"(a0), "r"(a1), "r"(a2), "r"(a3), "r"(b0), "r"(b1));
}

// ---------------- kernel 1: fused W fake-quant + H fp32->fp16 convert ----------------
// blocks [0,1024): one W output-channel each; blocks [1024, 1024+65536): H conversion.
// Streaming hints: H is read-once (__ldcs), g_h written-once-then-reread-later (__stcs),
// keeping the 384 MB stream from thrashing L2.
__global__ void prep_kernel(const float* __restrict__ W, const float* __restrict__ H) {
    int tid = threadIdx.x;
    if (blockIdx.x < NDIM) {
        int d = blockIdx.x;
        const float4* row4 = reinterpret_cast<const float4*>(W + (size_t)d * KDIM);
        float4 f[4];
        float m = 0.f;
        #pragma unroll
        for (int i = 0; i < 4; i++) {
            f[i] = __ldcs(&row4[i * 256 + tid]);
            m = fmaxf(m, fmaxf(fmaxf(fabsf(f[i].x), fabsf(f[i].y)),
                               fmaxf(fabsf(f[i].z), fabsf(f[i].w))));
        }
        #pragma unroll
        for (int o = 16; o; o >>= 1) m = fmaxf(m, __shfl_xor_sync(0xffffffffu, m, o));

        __shared__ float red[8];
        if ((tid & 31) == 0) red[tid >> 5] = m;
        __syncthreads();
        if (tid < 8) {
            float v = red[tid];
            #pragma unroll
            for (int o = 4; o; o >>= 1) v = fmaxf(v, __shfl_xor_sync(0xffu, v, o));
            if (tid == 0) red[0] = v;
        }
        __syncthreads();

        float scale = fmaxf(red[0], 1e-8f) / 127.f;
        if (tid == 0) g_scale[d] = scale;

        uint2* wout = reinterpret_cast<uint2*>(g_w + (size_t)d * KDIM);
        #pragma unroll
        for (int i = 0; i < 4; i++) {
            float qx = fminf(fmaxf(rintf(f[i].x / scale), -128.f), 127.f);
            float qy = fminf(fmaxf(rintf(f[i].y / scale), -128.f), 127.f);
            float qz = fminf(fmaxf(rintf(f[i].z / scale), -128.f), 127.f);
            float qw = fminf(fmaxf(rintf(f[i].w / scale), -128.f), 127.f);
            __half2 lo = __floats2half2_rn(qx, qy);    // exact ints in fp16
            __half2 hi = __floats2half2_rn(qz, qw);
            uint2 o;
            o.x = *reinterpret_cast<uint32_t*>(&lo);
            o.y = *reinterpret_cast<uint32_t*>(&hi);
            wout[i * 256 + tid] = o;
        }
    } else {
        size_t i = (size_t)(blockIdx.x - NDIM) * 256 + tid;   // float4 index
        float4 v = __ldcs(reinterpret_cast<const float4*>(H) + i);
        __half2 lo = __floats2half2_rn(v.x, v.y);
        __half2 hi = __floats2half2_rn(v.z, v.w);
        uint2 o;
        o.x = *reinterpret_cast<uint32_t*>(&lo);
        o.y = *reinterpret_cast<uint32_t*>(&hi);
        __stcs(reinterpret_cast<uint2*>(g_h) + i, o);
    }
}

// ---------------- kernel 2: fp16 mma.sync GEMM + scale/bias/residual epilogue ----------------
// CTA 128x128, BK=64, 8 warps in 2(m) x 4(n), warp tile 64x32, ldmatrix feeds. (R4 schedule)
__device__ __forceinline__ void load_stage(uint32_t stage_base, int tid, int m0, int n0, int t) {
    int k0 = t * BK;
    const __half* Ab = reinterpret_cast<const __half*>(g_h) + (size_t)m0 * KDIM + k0;
    #pragma unroll
    for (int i = 0; i < 4; i++) {
        int cid = i * 256 + tid;          // 1024 chunks of 16B
        int row = cid >> 3, col = cid & 7;
        cp16(stage_base + row * ROWB + col * 16, Ab + (size_t)row * KDIM + col * 8);
    }
    const __half* Bb = reinterpret_cast<const __half*>(g_w) + (size_t)n0 * KDIM + k0;
    uint32_t bbase = stage_base + A_STAGE_B;
    #pragma unroll
    for (int i = 0; i < 4; i++) {
        int cid = i * 256 + tid;
        int row = cid >> 3, col = cid & 7;
        cp16(bbase + row * ROWB + col * 16, Bb + (size_t)row * KDIM + col * 8);
    }
}

__global__ void __launch_bounds__(256, 2) gemm_kernel(const float* __restrict__ bias,
                                                      const float* __restrict__ input,
                                                      float* __restrict__ out) {
    extern __shared__ char smem[];
    uint32_t sb = smem_u32(smem);
    int tid = threadIdx.x;
    int wid = tid >> 5, lane = tid & 31;
    int g = lane >> 2, c = lane & 3;      // mma group / thread-in-group
    int wm = wid & 1, wn = wid >> 1;      // 2 x 4 warp grid

    int mtile = blockIdx.x >> 3;          // 128 m-tiles
    int ntile = blockIdx.x & 7;           // 8 n-tiles (adjacent bids share A tile in L2)
    int m0 = mtile * BM, n0 = ntile * BN;

    float* s_scale = reinterpret_cast<float*>(smem);
    float* s_bias  = reinterpret_cast<float*>(smem + 512);
    if (tid < 128) {
        s_scale[tid] = g_scale[n0 + tid];
        s_bias[tid]  = bias[n0 + tid];
    }

    // per-lane ldmatrix byte offsets (within a stage)
    uint32_t a_loff = (uint32_t)((wm * 64 + (lane & 15)) * ROWB + (lane >> 4) * 16);
    uint32_t b_loff = (uint32_t)(A_STAGE_B +
                      (wn * 32 + (lane >> 4) * 8 + (lane & 7)) * ROWB +
                      (((lane >> 3) & 1) * 16));

    // prologue
    #pragma unroll
    for (int s = 0; s < NSTAGE; s++) {
        load_stage(sb + 1024u + (uint32_t)s * STAGE_B, tid, m0, n0, s);
        cp_commit();
    }

    float acc[4][4][4];
    #pragma unroll
    for (int mt = 0; mt < 4; mt++)
        #pragma unroll
        for (int nt = 0; nt < 4; nt++)
            #pragma unroll
            for (int r = 0; r < 4; r++) acc[mt][nt][r] = 0.f;

    for (int t = 0; t < KT; t++) {
        int s = t % NSTAGE;
        uint32_t stage = sb + 1024u + (uint32_t)s * STAGE_B;

        cp_wait<NSTAGE - 1>();
        __syncthreads();

        #pragma unroll
        for (int ks = 0; ks < 4; ks++) {           // k offset ks*16 within BK=64
            uint32_t a[4][4], b[2][4];
            #pragma unroll
            for (int mt = 0; mt < 4; mt++)
                ldsm4(a[mt][0], a[mt][1], a[mt][2], a[mt][3],
                      stage + a_loff + (uint32_t)(mt * 16 * ROWB) + (uint32_t)(ks * 32));
            #pragma unroll
            for (int p = 0; p < 2; p++)
                ldsm4(b[p][0], b[p][1], b[p][2], b[p][3],
                      stage + b_loff + (uint32_t)(p * 16 * ROWB) + (uint32_t)(ks * 32));
            #pragma unroll
            for (int mt = 0; mt < 4; mt++)
                #pragma unroll
                for (int nt = 0; nt < 4; nt++) {
                    int p = nt >> 1, q = nt & 1;
                    mma16816(acc[mt][nt][0], acc[mt][nt][1], acc[mt][nt][2], acc[mt][nt][3],
                             a[mt][0], a[mt][1], a[mt][2], a[mt][3],
                             b[p][2 * q], b[p][2 * q + 1]);
                }
        }

        __syncthreads();                 // everyone done reading stage s
        if (t + NSTAGE < KT)
            load_stage(stage, tid, m0, n0, t + NSTAGE);
        cp_commit();                     // empty group in tail keeps accounting exact
    }

    // epilogue: out = acc * scale[n] + bias[n] + input
    #pragma unroll
    for (int mt = 0; mt < 4; mt++) {
        #pragma unroll
        for (int nt = 0; nt < 4; nt++) {
            int nl = wn * 32 + nt * 8 + 2 * c;
            int n  = n0 + nl;
            float sc0 = s_scale[nl],     sc1 = s_scale[nl + 1];
            float bi0 = s_bias[nl],      bi1 = s_bias[nl + 1];
            int mA = m0 + wm * 64 + mt * 16 + g;
            int mB = mA + 8;

            const float2* inA = reinterpret_cast<const float2*>(input + (size_t)mA * NDIM + n);
            const float2* inB = reinterpret_cast<const float2*>(input + (size_t)mB * NDIM + n);
            float2* outA = reinterpret_cast<float2*>(out + (size_t)mA * NDIM + n);
            float2* outB = reinterpret_cast<float2*>(out + (size_t)mB * NDIM + n);

            float2 ia = __ldcs(inA), ib = __ldcs(inB), oa, ob;
            oa.x = acc[mt][nt][0] * sc0 + bi0 + ia.x;
            oa.y = acc[mt][nt][1] * sc1 + bi1 + ia.y;
            ob.x = acc[mt][nt][2] * sc0 + bi0 + ib.x;
            ob.y = acc[mt][nt][3] * sc1 + bi1 + ib.y;
            __stcs(outA, oa);
            __stcs(outB, ob);
        }
    }
}

// ---------------- launch ----------------
extern "C" void kernel_launch(void* const* d_in, const int* in_sizes, int n_in,
                              void* d_out, int out_size) {
    const float* hidden = (const float*)d_in[0];   // [16,1024,4096]
    const float* input  = (const float*)d_in[1];   // [16,1024,1024]
    const float* W      = (const float*)d_in[2];   // [1024,4096]
    const float* b      = (const float*)d_in[3];   // [1024]
    float* out = (float*)d_out;

    prep_kernel<<<NDIM + (int)((size_t)MDIM * KDIM / 4 / 256), 256>>>(W, hidden);

    cudaFuncSetAttribute(gemm_kernel, cudaFuncAttributeMaxDynamicSharedMemorySize, SMEM_BYTES);
    gemm_kernel<<<(MDIM / BM) * (NDIM / BN), 256, SMEM_BYTES>>>(b, input, out);
}